// round 5
// baseline (speedup 1.0000x reference)
#include <cuda_runtime.h>

// Problem constants (BETA = ALPHA = WEIGHT = 1 are compile-time constants in the reference)
#define N_POINTS 4096
#define N_EVENTS 1000000

#define THREADS      256
#define PAIR_BLOCKS  2048           // folded triangular rows: block b -> rows {b, 4094-b}
#define EVENT_BLOCKS 512
#define TOTAL_BLOCKS (PAIR_BLOCKS + EVENT_BLOCKS)

__device__ float g_partials[TOTAL_BLOCKS];

__device__ __forceinline__ float block_reduce_sum(float v) {
    __shared__ float sdata[THREADS / 32];
    #pragma unroll
    for (int o = 16; o > 0; o >>= 1) v += __shfl_down_sync(0xffffffffu, v, o);
    const int lane = threadIdx.x & 31;
    const int wid  = threadIdx.x >> 5;
    if (lane == 0) sdata[wid] = v;
    __syncthreads();
    if (wid == 0) {
        v = (lane < THREADS / 32) ? sdata[lane] : 0.0f;
        #pragma unroll
        for (int o = (THREADS / 64); o > 0; o >>= 1) v += __shfl_down_sync(0xffffffffu, v, o);
    }
    return v;
}

__global__ __launch_bounds__(THREADS)
void smallnet_main_kernel(const float2* __restrict__ z0,
                          const float2* __restrict__ v0,
                          const float*  __restrict__ event_times,
                          const float*  __restrict__ t0p,
                          const float*  __restrict__ tnp,
                          const int*    __restrict__ u_idx,
                          const int*    __restrict__ v_idx) {
    float acc = 0.0f;
    const int b = blockIdx.x;

    if (b < PAIR_BLOCKS) {
        // ---- non-event (pair) term ----
        const float t0 = __ldg(t0p);
        const float tn = __ldg(tnp);
        const float SQRT_PI = 1.7724538509055160f;

        #pragma unroll
        for (int pass = 0; pass < 2; ++pass) {
            const int i = (pass == 0) ? b : (N_POINTS - 2 - b);
            if (pass == 1 && i <= b) break;   // b == 2047 folds onto itself: do it once

            const float2 zi = __ldg(&z0[i]);
            const float2 vi = __ldg(&v0[i]);

            for (int j = i + 1 + threadIdx.x; j < N_POINTS; j += THREADS) {
                const float2 zj = __ldg(&z0[j]);
                const float2 vj = __ldg(&v0[j]);

                const float a  = zi.x - zj.x;
                const float bb = zi.y - zj.y;
                const float m  = vi.x - vj.x;
                const float n  = vi.y - vj.y;

                const float mn2   = m * m + n * n;
                const float s     = sqrtf(mn2);                  // alpha = 1
                const float cross = a * n - bb * m;
                const float dot   = a * m + bb * n;

                // exp((-cross^2 * alpha + mn2 * beta) / mn2), alpha = beta = 1
                const float expo = expf((mn2 - cross * cross) / mn2);

                const float inv_s = 1.0f / s;
                const float e0 = erff((mn2 * t0 + dot) * inv_s);
                const float e1 = erff((mn2 * tn + dot) * inv_s);

                // integral = -sqrt(pi) * expo * (erf(a0) - erf(a1)) / (2 s)
                acc += -SQRT_PI * expo * (e0 - e1) * (0.5f * inv_s);
            }
        }
        // output subtracts the non-event sum -> negate here
        const float tot = block_reduce_sum(acc);
        if (threadIdx.x == 0) g_partials[b] = -tot;
    } else {
        // ---- event term: sum_e (beta - ||dz0 + dv0*t||^2) ----
        const int eb = b - PAIR_BLOCKS;
        for (int e = eb * THREADS + threadIdx.x; e < N_EVENTS; e += EVENT_BLOCKS * THREADS) {
            const int u = __ldg(&u_idx[e]);
            const int v = __ldg(&v_idx[e]);
            const float t = __ldg(&event_times[e]);

            const float2 zu = __ldg(&z0[u]);
            const float2 zv = __ldg(&z0[v]);
            const float2 vu = __ldg(&v0[u]);
            const float2 vv = __ldg(&v0[v]);

            const float dx = (zu.x - zv.x) + (vu.x - vv.x) * t;
            const float dy = (zu.y - zv.y) + (vu.y - vv.y) * t;
            acc += 1.0f - (dx * dx + dy * dy);   // beta = 1
        }
        const float tot = block_reduce_sum(acc);
        if (threadIdx.x == 0) g_partials[b] = tot;
    }
}

__global__ __launch_bounds__(THREADS)
void smallnet_reduce_kernel(float* __restrict__ out) {
    float acc = 0.0f;
    for (int i = threadIdx.x; i < TOTAL_BLOCKS; i += THREADS) acc += g_partials[i];
    acc = block_reduce_sum(acc);
    if (threadIdx.x == 0) out[0] = acc;
}

extern "C" void kernel_launch(void* const* d_in, const int* in_sizes, int n_in,
                              void* d_out, int out_size) {
    // metadata order: z0[4096,2], v0[4096,2], event_times[1e6], t0[], tn[], u_idx[1e6], v_idx[1e6]
    const float2* z0 = (const float2*)d_in[0];
    const float2* v0 = (const float2*)d_in[1];
    const float*  et = (const float*)d_in[2];
    const float*  t0 = (const float*)d_in[3];
    const float*  tn = (const float*)d_in[4];
    const int*    ui = (const int*)d_in[5];
    const int*    vi = (const int*)d_in[6];
    float* out = (float*)d_out;

    smallnet_main_kernel<<<TOTAL_BLOCKS, THREADS>>>(z0, v0, et, t0, tn, ui, vi);
    smallnet_reduce_kernel<<<1, THREADS>>>(out);
}

// round 7
// speedup vs baseline: 1.0008x; 1.0008x over previous
#include <cuda_runtime.h>

// Problem constants (BETA = ALPHA = WEIGHT = 1 are compile-time constants in the reference)
#define N_POINTS 4096
#define N_EVENTS 1000000

#define THREADS      256
#define ROWPAIRS     2048                       // folded rows: rp -> rows {rp, 4094-rp}
#define PAIR_SPLIT   2                          // blocks per folded row-pair (tail granularity)
#define PAIR_BLOCKS  (ROWPAIRS * PAIR_SPLIT)    // 4096
#define EVENT_BLOCKS 512
#define TOTAL_BLOCKS (PAIR_BLOCKS + EVENT_BLOCKS)

__device__ float        g_partials[TOTAL_BLOCKS];
__device__ unsigned int g_count;   // zero-init; last block resets it -> graph-replay safe

__device__ __forceinline__ float block_reduce_sum(float v) {
    __shared__ float sdata[THREADS / 32];
    #pragma unroll
    for (int o = 16; o > 0; o >>= 1) v += __shfl_down_sync(0xffffffffu, v, o);
    const int lane = threadIdx.x & 31;
    const int wid  = threadIdx.x >> 5;
    if (lane == 0) sdata[wid] = v;
    __syncthreads();
    if (wid == 0) {
        v = (lane < THREADS / 32) ? sdata[lane] : 0.0f;
        #pragma unroll
        for (int o = (THREADS / 64); o > 0; o >>= 1) v += __shfl_down_sync(0xffffffffu, v, o);
    }
    return v;
}

// Abramowitz & Stegun 7.1.26, |abs err| <= 1.5e-7 on all x. ~9 FFMA + RCP + EX2.
__device__ __forceinline__ float erf_fast(float x) {
    const float ax = fabsf(x);
    const float t  = __fdividef(1.0f, fmaf(0.3275911f, ax, 1.0f));
    float p = fmaf(1.061405429f, t, -1.453152027f);
    p = fmaf(p, t,  1.421413741f);
    p = fmaf(p, t, -0.284496736f);
    p = fmaf(p, t,  0.254829592f);
    p = p * t;
    const float r = fmaf(-p, __expf(-ax * ax), 1.0f);
    return copysignf(r, x);
}

__global__ __launch_bounds__(THREADS)
void smallnet_fused_kernel(const float2* __restrict__ z0,
                           const float2* __restrict__ v0,
                           const float*  __restrict__ event_times,
                           const float*  __restrict__ t0p,
                           const float*  __restrict__ tnp,
                           const int*    __restrict__ u_idx,
                           const int*    __restrict__ v_idx,
                           float* __restrict__ out) {
    float acc = 0.0f;
    const int b = blockIdx.x;
    float partial;

    if (b < PAIR_BLOCKS) {
        // ---- non-event (pair) term ----
        const float t0 = __ldg(t0p);
        const float tn = __ldg(tnp);
        const int rp   = b >> 1;            // folded row pair
        const int half = b & 1;             // which half of the j-range

        #pragma unroll
        for (int pass = 0; pass < 2; ++pass) {
            const int i = (pass == 0) ? rp : (N_POINTS - 2 - rp);
            if (pass == 1 && i <= rp) break;     // rp == 2047 folds onto itself

            const float2 zi = __ldg(&z0[i]);
            const float2 vi = __ldg(&v0[i]);

            for (int j = i + 1 + half * THREADS + threadIdx.x; j < N_POINTS;
                 j += PAIR_SPLIT * THREADS) {
                const float2 zj = __ldg(&z0[j]);
                const float2 vj = __ldg(&v0[j]);

                const float a  = zi.x - zj.x;
                const float bb = zi.y - zj.y;
                const float m  = vi.x - vj.x;
                const float n  = vi.y - vj.y;

                const float mn2     = fmaf(m, m, n * n);
                const float inv_s   = rsqrtf(mn2);          // alpha = 1
                const float inv_mn2 = inv_s * inv_s;
                const float cross   = fmaf(a, n, -bb * m);
                const float dot     = fmaf(a, m,  bb * n);

                // exp((mn2 - cross^2)/mn2) = exp(1 - cross^2/mn2)
                const float expo = __expf(fmaf(-cross * cross, inv_mn2, 1.0f));

                const float x0 = fmaf(mn2, t0, dot) * inv_s;
                const float x1 = fmaf(mn2, tn, dot) * inv_s;
                const float ed = erf_fast(x1) - erf_fast(x0);   // >= 0

                acc = fmaf(expo * ed, inv_s, acc);
            }
        }
        const float tot = block_reduce_sum(acc);
        // integral_sum = sqrt(pi)/2 * tot; output subtracts it -> negate
        partial = -0.88622692545275801f * tot;
    } else {
        // ---- event term: sum_e (beta - ||dz0 + dv0*t||^2), vectorized x4 ----
        const int eb = b - PAIR_BLOCKS;
        const int4*   u4 = (const int4*)u_idx;
        const int4*   v4 = (const int4*)v_idx;
        const float4* t4 = (const float4*)event_times;
        const int nvec = N_EVENTS / 4;

        for (int e = eb * THREADS + threadIdx.x; e < nvec; e += EVENT_BLOCKS * THREADS) {
            const int4   u = __ldg(&u4[e]);
            const int4   v = __ldg(&v4[e]);
            const float4 t = __ldg(&t4[e]);

            #pragma unroll
            for (int k = 0; k < 4; ++k) {
                const int   uu = (&u.x)[k];
                const int   vv = (&v.x)[k];
                const float tt = (&t.x)[k];
                const float2 zu = __ldg(&z0[uu]);
                const float2 zv = __ldg(&z0[vv]);
                const float2 vu = __ldg(&v0[uu]);
                const float2 vw = __ldg(&v0[vv]);
                const float dx = fmaf(vu.x - vw.x, tt, zu.x - zv.x);
                const float dy = fmaf(vu.y - vw.y, tt, zu.y - zv.y);
                acc += 1.0f - fmaf(dx, dx, dy * dy);   // beta = 1
            }
        }
        partial = block_reduce_sum(acc);
    }

    // ---- grid-wide deterministic reduction: last block sums all partials ----
    __shared__ bool is_last;
    if (threadIdx.x == 0) {
        g_partials[b] = partial;
        __threadfence();
        const unsigned int old = atomicAdd(&g_count, 1u);
        is_last = (old == (unsigned int)(TOTAL_BLOCKS - 1));
    }
    __syncthreads();

    if (is_last) {
        __threadfence();
        float s = 0.0f;
        for (int i = threadIdx.x; i < TOTAL_BLOCKS; i += THREADS) s += g_partials[i];
        s = block_reduce_sum(s);
        if (threadIdx.x == 0) {
            out[0]  = s;
            g_count = 0;   // reset for next graph replay
        }
    }
}

extern "C" void kernel_launch(void* const* d_in, const int* in_sizes, int n_in,
                              void* d_out, int out_size) {
    // metadata order: z0[4096,2], v0[4096,2], event_times[1e6], t0[], tn[], u_idx[1e6], v_idx[1e6]
    const float2* z0 = (const float2*)d_in[0];
    const float2* v0 = (const float2*)d_in[1];
    const float*  et = (const float*)d_in[2];
    const float*  t0 = (const float*)d_in[3];
    const float*  tn = (const float*)d_in[4];
    const int*    ui = (const int*)d_in[5];
    const int*    vi = (const int*)d_in[6];
    float* out = (float*)d_out;

    smallnet_fused_kernel<<<TOTAL_BLOCKS, THREADS>>>(z0, v0, et, t0, tn, ui, vi, out);
}

// round 8
// speedup vs baseline: 1.3292x; 1.3282x over previous
#include <cuda_runtime.h>
#include <cuda_fp16.h>

// Problem constants (BETA = ALPHA = WEIGHT = 1 are compile-time constants in the reference)
#define N_POINTS 4096
#define N_EVENTS 1000000

#define THREADS      256
#define EVENT_BLOCKS 128                        // placed FIRST in the grid (overlap with pairs)
#define ROWPAIRS     2048                       // folded rows: rp -> rows {rp, 4094-rp}
#define PAIR_SPLIT   2
#define PAIR_BLOCKS  (ROWPAIRS * PAIR_SPLIT)    // 4096
#define TOTAL_BLOCKS (EVENT_BLOCKS + PAIR_BLOCKS)

__device__ float        g_partials[TOTAL_BLOCKS];
__device__ unsigned int g_count;   // zero-init; last block resets it -> graph-replay safe

__device__ __forceinline__ float block_reduce_sum(float v) {
    __shared__ float sdata[THREADS / 32];
    #pragma unroll
    for (int o = 16; o > 0; o >>= 1) v += __shfl_down_sync(0xffffffffu, v, o);
    const int lane = threadIdx.x & 31;
    const int wid  = threadIdx.x >> 5;
    if (lane == 0) sdata[wid] = v;
    __syncthreads();
    if (wid == 0) {
        v = (lane < THREADS / 32) ? sdata[lane] : 0.0f;
        #pragma unroll
        for (int o = (THREADS / 64); o > 0; o >>= 1) v += __shfl_down_sync(0xffffffffu, v, o);
    }
    return v;
}

__global__ __launch_bounds__(THREADS)
void smallnet_fused_kernel(const float2* __restrict__ z0,
                           const float2* __restrict__ v0,
                           const float*  __restrict__ event_times,
                           const float*  __restrict__ t0p,
                           const float*  __restrict__ tnp,
                           const int*    __restrict__ u_idx,
                           const int*    __restrict__ v_idx,
                           float* __restrict__ out) {
    // fp16 node table for event gathers: (z.x,z.y) in .x, (v.x,v.y) in .y  (32 KB)
    __shared__ uint2 tbl[N_POINTS];

    float acc = 0.0f;
    const int b = blockIdx.x;
    float partial;

    if (b >= EVENT_BLOCKS) {
        // ================= non-event (pair) term: GL-4 quadrature =================
        // I = (dt/2) * sum_k w_k * exp(E - u_k^2),  E = 1 - cross^2/mn2,
        // u_k = x0 + s*dt*c_k,  x0 = (mn2*t0 + dot)/s,  s = sqrt(mn2)
        const float t0 = __ldg(t0p);
        const float tn = __ldg(tnp);
        const float dt = tn - t0;

        const float L  = 1.4426950408889634f;   // log2(e)
        const float SL = 1.2011224087864498f;   // sqrt(log2(e))
        // GL-4 nodes mapped to [0,1] and weights
        const float C0 = 0.06943184420297371f, C1 = 0.33000947820757187f;
        const float C2 = 0.66999052179242810f, C3 = 0.93056815579702620f;
        const float W0 = 0.3478548451374538f,  W1 = 0.6521451548625461f;

        const float dtSL = dt * SL;
        const int pb   = b - EVENT_BLOCKS;
        const int rp   = pb >> 1;           // folded row pair
        const int half = pb & 1;            // which half of the j-range

        #pragma unroll
        for (int pass = 0; pass < 2; ++pass) {
            const int i = (pass == 0) ? rp : (N_POINTS - 2 - rp);
            if (pass == 1 && i <= rp) break;     // rp == 2047 folds onto itself

            const float2 zi = __ldg(&z0[i]);
            const float2 vi = __ldg(&v0[i]);

            #pragma unroll 2
            for (int j = i + 1 + half * THREADS + threadIdx.x; j < N_POINTS;
                 j += PAIR_SPLIT * THREADS) {
                const float2 zj = __ldg(&z0[j]);
                const float2 vj = __ldg(&v0[j]);

                const float a  = zi.x - zj.x;
                const float bb = zi.y - zj.y;
                const float m  = vi.x - vj.x;
                const float n  = vi.y - vj.y;

                const float mn2   = fmaf(m, m, n * n);
                const float inv_s = rsqrtf(mn2);             // alpha = 1
                const float cross = fmaf(a, n, -bb * m);
                const float dot   = fmaf(a, m,  bb * n);

                const float s    = mn2 * inv_s;
                const float isSL = inv_s * SL;
                const float x0s  = fmaf(mn2, t0, dot) * isSL;   // x0 * sqrt(L)
                const float dS   = s * dtSL;                    // (x1-x0) * sqrt(L)

                const float cc   = cross * cross;
                const float im2  = inv_s * inv_s;
                const float q    = cc * im2;
                const float Elog = fmaf(-L, q, L);              // L*(1 - cross^2/mn2)

                const float u0 = fmaf(C0, dS, x0s);
                const float u1 = fmaf(C1, dS, x0s);
                const float u2 = fmaf(C2, dS, x0s);
                const float u3 = fmaf(C3, dS, x0s);

                const float e0 = exp2f(fmaf(-u0, u0, Elog));
                const float e1 = exp2f(fmaf(-u1, u1, Elog));
                const float e2 = exp2f(fmaf(-u2, u2, Elog));
                const float e3 = exp2f(fmaf(-u3, u3, Elog));

                float g = W0 * e0;
                g = fmaf(W1, e1, g);
                g = fmaf(W1, e2, g);
                g = fmaf(W0, e3, g);
                acc += g;
            }
        }
        const float tot = block_reduce_sum(acc);
        // integral_sum = (dt/2) * tot; output subtracts it -> negate
        partial = -0.5f * dt * tot;
    } else {
        // ================= event term: sum_e (1 - ||dz0 + dv0*t||^2) =================
        // Build fp16 node table in shared (coalesced), then gather via LDS.64.
        for (int p = threadIdx.x; p < N_POINTS; p += THREADS) {
            const float2 z = __ldg(&z0[p]);
            const float2 v = __ldg(&v0[p]);
            __half2 hz = __floats2half2_rn(z.x, z.y);
            __half2 hv = __floats2half2_rn(v.x, v.y);
            uint2 e;
            e.x = *reinterpret_cast<unsigned int*>(&hz);
            e.y = *reinterpret_cast<unsigned int*>(&hv);
            tbl[p] = e;
        }
        __syncthreads();

        const int4*   u4 = (const int4*)u_idx;
        const int4*   v4 = (const int4*)v_idx;
        const float4* t4 = (const float4*)event_times;
        const int nvec = N_EVENTS / 4;

        for (int e = b * THREADS + threadIdx.x; e < nvec; e += EVENT_BLOCKS * THREADS) {
            const int4   u = __ldg(&u4[e]);
            const int4   v = __ldg(&v4[e]);
            const float4 t = __ldg(&t4[e]);

            #pragma unroll
            for (int k = 0; k < 4; ++k) {
                const uint2 eu = tbl[(&u.x)[k]];
                const uint2 ev = tbl[(&v.x)[k]];
                const float tt = (&t.x)[k];

                const __half2 hzu = *reinterpret_cast<const __half2*>(&eu.x);
                const __half2 hvu = *reinterpret_cast<const __half2*>(&eu.y);
                const __half2 hzv = *reinterpret_cast<const __half2*>(&ev.x);
                const __half2 hvv = *reinterpret_cast<const __half2*>(&ev.y);

                const float2 dz = __half22float2(__hsub2(hzu, hzv));
                const float2 dv = __half22float2(__hsub2(hvu, hvv));

                const float dx = fmaf(dv.x, tt, dz.x);
                const float dy = fmaf(dv.y, tt, dz.y);
                acc += 1.0f - fmaf(dx, dx, dy * dy);   // beta = 1
            }
        }
        partial = block_reduce_sum(acc);
    }

    // ---- grid-wide deterministic reduction: last block sums all partials ----
    __shared__ bool is_last;
    if (threadIdx.x == 0) {
        g_partials[b] = partial;
        __threadfence();
        const unsigned int old = atomicAdd(&g_count, 1u);
        is_last = (old == (unsigned int)(TOTAL_BLOCKS - 1));
    }
    __syncthreads();

    if (is_last) {
        __threadfence();
        float s = 0.0f;
        for (int i = threadIdx.x; i < TOTAL_BLOCKS; i += THREADS) s += g_partials[i];
        s = block_reduce_sum(s);
        if (threadIdx.x == 0) {
            out[0]  = s;
            g_count = 0;   // reset for next graph replay
        }
    }
}

extern "C" void kernel_launch(void* const* d_in, const int* in_sizes, int n_in,
                              void* d_out, int out_size) {
    // metadata order: z0[4096,2], v0[4096,2], event_times[1e6], t0[], tn[], u_idx[1e6], v_idx[1e6]
    const float2* z0 = (const float2*)d_in[0];
    const float2* v0 = (const float2*)d_in[1];
    const float*  et = (const float*)d_in[2];
    const float*  t0 = (const float*)d_in[3];
    const float*  tn = (const float*)d_in[4];
    const int*    ui = (const int*)d_in[5];
    const int*    vi = (const int*)d_in[6];
    float* out = (float*)d_out;

    smallnet_fused_kernel<<<TOTAL_BLOCKS, THREADS>>>(z0, v0, et, t0, tn, ui, vi, out);
}